// round 2
// baseline (speedup 1.0000x reference)
#include <cuda_runtime.h>

#define G_N   8192
#define NH    8
#define HDIM  64
#define AD    512
#define GFDIM 32
#define CIMG  256
#define IMG   64
#define NPIX  (IMG*IMG)
#define KPTS  12
#define SIGC  9.21f

// Scratch (static device globals: allocation-free rule)
__device__ float g_q[G_N * 3 * AD];         // [g][t][a]   ~50 MB
__device__ float g_kv[NH * NPIX * 128];     // [h][pix][k0..63, v0..63]  16 MB
__device__ float g_attn[G_N * 3 * AD];      // [g][t][h*64+d]  ~50 MB

__constant__ float c_fix[18] = {0,0,0, 1,0,0, 0,1,0, 0,0,1, -1,0,0, 0,-1,0};

// ---------------------------------------------------------------------------
// Kernel A: kmap/vmap = Wk/Wv @ image_features, written interleaved
//   [h][pix][d] (k) and [h][pix][64+d] (v).  M=4096 pixels, N=512, K=256.
//   Tile BM=64 x BN=128, TK=16, thread tile 4x8 per map.
// ---------------------------------------------------------------------------
__global__ __launch_bounds__(256) void kv_gemm(
    const float* __restrict__ img, const float* __restrict__ Wk,
    const float* __restrict__ Wv)
{
    const int m0 = blockIdx.x * 64;
    const int n0 = blockIdx.y * 128;
    __shared__ float As[16][64];
    __shared__ float Bks[16][128];
    __shared__ float Bvs[16][128];
    const int t  = threadIdx.x;
    const int tx = t & 15, ty = t >> 4;

    float ak[4][8], av[4][8];
#pragma unroll
    for (int i = 0; i < 4; i++)
#pragma unroll
        for (int j = 0; j < 8; j++) { ak[i][j] = 0.f; av[i][j] = 0.f; }

    for (int c0 = 0; c0 < CIMG; c0 += 16) {
        // As[kk][mm] = img[(c0+kk)*4096 + m0+mm]
        *(float4*)&As[ty][tx * 4] =
            *(const float4*)(img + (size_t)(c0 + ty) * NPIX + m0 + tx * 4);
        // B[kk][nn] = W[(n0+nn)*256 + c0+kk], transposed-on-store
#pragma unroll
        for (int rep = 0; rep < 2; rep++) {
            int idx = t + rep * 256;
            int nn  = idx >> 2;
            int kk4 = (idx & 3) * 4;
            float4 wk = *(const float4*)(Wk + (size_t)(n0 + nn) * CIMG + c0 + kk4);
            float4 wv = *(const float4*)(Wv + (size_t)(n0 + nn) * CIMG + c0 + kk4);
            Bks[kk4 + 0][nn] = wk.x; Bks[kk4 + 1][nn] = wk.y;
            Bks[kk4 + 2][nn] = wk.z; Bks[kk4 + 3][nn] = wk.w;
            Bvs[kk4 + 0][nn] = wv.x; Bvs[kk4 + 1][nn] = wv.y;
            Bvs[kk4 + 2][nn] = wv.z; Bvs[kk4 + 3][nn] = wv.w;
        }
        __syncthreads();
#pragma unroll
        for (int kk = 0; kk < 16; kk++) {
            float4 a4  = *(float4*)&As[kk][ty * 4];
            float4 bk0 = *(float4*)&Bks[kk][tx * 4];
            float4 bk1 = *(float4*)&Bks[kk][tx * 4 + 64];
            float4 bv0 = *(float4*)&Bvs[kk][tx * 4];
            float4 bv1 = *(float4*)&Bvs[kk][tx * 4 + 64];
            float a[4]  = {a4.x, a4.y, a4.z, a4.w};
            float bk[8] = {bk0.x, bk0.y, bk0.z, bk0.w, bk1.x, bk1.y, bk1.z, bk1.w};
            float bv[8] = {bv0.x, bv0.y, bv0.z, bv0.w, bv1.x, bv1.y, bv1.z, bv1.w};
#pragma unroll
            for (int i = 0; i < 4; i++)
#pragma unroll
                for (int j = 0; j < 8; j++) {
                    ak[i][j] += a[i] * bk[j];
                    av[i][j] += a[i] * bv[j];
                }
        }
        __syncthreads();
    }
#pragma unroll
    for (int i = 0; i < 4; i++) {
        int m = m0 + ty * 4 + i;
#pragma unroll
        for (int q = 0; q < 2; q++) {
            int h = (n0 >> 6) + q;
            float* dst = g_kv + (size_t)(h * NPIX + m) * 128 + tx * 4;
            *(float4*)dst =
                make_float4(ak[i][q*4+0], ak[i][q*4+1], ak[i][q*4+2], ak[i][q*4+3]);
            *(float4*)(dst + 64) =
                make_float4(av[i][q*4+0], av[i][q*4+1], av[i][q*4+2], av[i][q*4+3]);
        }
    }
}

// ---------------------------------------------------------------------------
// Kernel B: q = features @ Wq.  M=24576, K=32, N=512.
// ---------------------------------------------------------------------------
__global__ __launch_bounds__(256) void q_gemm(
    const float* __restrict__ feat, const float* __restrict__ Wq)
{
    const int r0 = blockIdx.x * 64;
    const int n0 = blockIdx.y * 256;
    __shared__ float Fs[64][32];
    __shared__ float Ws[32][256];
    const int t = threadIdx.x;
#pragma unroll
    for (int rep = 0; rep < 8; rep++) {
        int idx = t + rep * 256;
        Fs[idx >> 5][idx & 31] = feat[(size_t)(r0 + (idx >> 5)) * GFDIM + (idx & 31)];
    }
#pragma unroll
    for (int rep = 0; rep < 8; rep++) {
        int idx = t + rep * 256;
        int k = idx >> 6, n4 = (idx & 63) << 2;
        *(float4*)&Ws[k][n4] = *(const float4*)(Wq + (size_t)k * AD + n0 + n4);
    }
    __syncthreads();

    const int tc = t & 15, tr = t >> 4;
    float acc[4][16];
#pragma unroll
    for (int i = 0; i < 4; i++)
#pragma unroll
        for (int j = 0; j < 16; j++) acc[i][j] = 0.f;

#pragma unroll
    for (int k = 0; k < 32; k++) {
        float f[4];
#pragma unroll
        for (int i = 0; i < 4; i++) f[i] = Fs[tr * 4 + i][k];
        float w[16];
#pragma unroll
        for (int q = 0; q < 4; q++) {
            float4 w4 = *(float4*)&Ws[k][q * 64 + tc * 4];
            w[q*4+0] = w4.x; w[q*4+1] = w4.y; w[q*4+2] = w4.z; w[q*4+3] = w4.w;
        }
#pragma unroll
        for (int i = 0; i < 4; i++)
#pragma unroll
            for (int j = 0; j < 16; j++) acc[i][j] += f[i] * w[j];
    }
#pragma unroll
    for (int i = 0; i < 4; i++) {
        int r = r0 + tr * 4 + i;
#pragma unroll
        for (int q = 0; q < 4; q++)
            *(float4*)&g_q[(size_t)r * AD + n0 + q * 64 + tc * 4] =
                make_float4(acc[i][q*4+0], acc[i][q*4+1], acc[i][q*4+2], acc[i][q*4+3]);
    }
}

// ---------------------------------------------------------------------------
// Kernel C: per-(gaussian, head) deformable attention.
//   1 warp per (g,h). Lanes 0-15 hold k channels (4 each), 16-31 hold v.
//   One LDG.128 per bilinear tap fetches 64 k + 64 v channels.
//   Streaming softmax (no running-max; scores are O(1)).
// ---------------------------------------------------------------------------
__global__ __launch_bounds__(256) void attn_kernel(
    const float* __restrict__ means, const float* __restrict__ scales,
    const float* __restrict__ rots, const float* __restrict__ transforms,
    const float* __restrict__ proj, const float* __restrict__ W_off,
    const float* __restrict__ b_off)
{
    const int g    = blockIdx.x;
    const int h    = threadIdx.x >> 5;
    const int lane = threadIdx.x & 31;
    __shared__ float sh_qm[NH][HDIM];
    __shared__ float sh_learn[NH][18];

    const int c4 = (lane & 15) * 4;
    const float* qrow = g_q + (size_t)g * 3 * AD + h * HDIM + c4;
    float4 q0 = *(const float4*)(qrow);
    float4 q1 = *(const float4*)(qrow + AD);
    float4 q2 = *(const float4*)(qrow + 2 * AD);

    if (lane < 16) {
        const float inv3 = 1.f / 3.f;
        sh_qm[h][c4 + 0] = (q0.x + q1.x + q2.x) * inv3;
        sh_qm[h][c4 + 1] = (q0.y + q1.y + q2.y) * inv3;
        sh_qm[h][c4 + 2] = (q0.z + q1.z + q2.z) * inv3;
        sh_qm[h][c4 + 3] = (q0.w + q1.w + q2.w) * inv3;
    }
    __syncwarp();

    float mx = means[g*3+0], my = means[g*3+1], mz = means[g*3+2];
    const float* T = transforms + (size_t)g * 16;
    float mwx = T[0]*mx + T[1]*my + T[2] *mz + T[3];
    float mwy = T[4]*mx + T[5]*my + T[6] *mz + T[7];
    float mwz = T[8]*mx + T[9]*my + T[10]*mz + T[11];

    // OffsetNet: lanes 0..17 each produce one of 18 outputs
    if (lane < 18) {
        float z = b_off[lane] + mwx*W_off[0*18+lane] + mwy*W_off[1*18+lane]
                + mwz*W_off[2*18+lane];
#pragma unroll 8
        for (int c = 0; c < HDIM; c++) z += sh_qm[h][c] * W_off[(3 + c) * 18 + lane];
        z = fminf(fmaxf(z, -SIGC), SIGC);
        sh_learn[h][lane] = 1.f / (1.f + __expf(-z)) - 0.5f;
    }
    __syncwarp();

    // Rotation matrix from normalized quaternion
    float qw = rots[g*4+0], qx = rots[g*4+1], qy = rots[g*4+2], qz = rots[g*4+3];
    float qn = rsqrtf(qw*qw + qx*qx + qy*qy + qz*qz);
    qw *= qn; qx *= qn; qy *= qn; qz *= qn;
    float r00 = 1.f-2.f*(qy*qy+qz*qz), r01 = 2.f*(qx*qy-qw*qz), r02 = 2.f*(qx*qz+qw*qy);
    float r10 = 2.f*(qx*qy+qw*qz), r11 = 1.f-2.f*(qx*qx+qz*qz), r12 = 2.f*(qy*qz-qw*qx);
    float r20 = 2.f*(qx*qz-qw*qy), r21 = 2.f*(qy*qz+qw*qx), r22 = 1.f-2.f*(qx*qx+qy*qy);

    float sx = scales[g*3+0], sy = scales[g*3+1], sz = scales[g*3+2];

    // Lane k (<12) computes sample point k; broadcast later via shfl
    float fx0 = 0.f, fy0 = 0.f, wx1 = 0.f, wy1 = 0.f;
    {
        int k = lane < 12 ? lane : 11;
        float s0, s1, s2;
        if (k < 6) { s0 = c_fix[k*3+0]; s1 = c_fix[k*3+1]; s2 = c_fix[k*3+2]; }
        else { int l = (k - 6) * 3;
               s0 = sh_learn[h][l]; s1 = sh_learn[h][l+1]; s2 = sh_learn[h][l+2]; }
        float v0 = s0 * sx, v1 = s1 * sy, v2 = s2 * sz;
        // world = R^T v + mw
        float px = r00*v0 + r10*v1 + r20*v2 + mwx;
        float py = r01*v0 + r11*v1 + r21*v2 + mwy;
        float pz = r02*v0 + r12*v1 + r22*v2 + mwz;
        float p0 = proj[0]*px + proj[1]*py + proj[2] *pz + proj[3];
        float p1 = proj[4]*px + proj[5]*py + proj[6] *pz + proj[7];
        float p2 = proj[8]*px + proj[9]*py + proj[10]*pz + proj[11];
        float zz = fmaxf(p2, 1e-5f);
        float u = p0 / zz, v = p1 / zz;
        const float lim = 0.9999f * (float)IMG;
        float xf = fminf(fmaxf(u, 0.f), lim) - 0.5f;   // pixel coords, align_corners=False
        float yf = fminf(fmaxf(v, 0.f), lim) - 0.5f;
        fx0 = floorf(xf); wx1 = xf - fx0;
        fy0 = floorf(yf); wy1 = yf - fy0;
    }

    const float* kvh = g_kv + (size_t)h * NPIX * 128;
    const int coff = ((lane < 16) ? 0 : 64) + c4;

    float s0v = 0.f, s1v = 0.f, s2v = 0.f;
    float4 o0 = make_float4(0,0,0,0), o1 = o0, o2 = o0;

#pragma unroll
    for (int kp = 0; kp < KPTS; kp++) {
        float bx0  = __shfl_sync(0xffffffffu, fx0, kp);
        float by0  = __shfl_sync(0xffffffffu, fy0, kp);
        float bwx1 = __shfl_sync(0xffffffffu, wx1, kp);
        float bwy1 = __shfl_sync(0xffffffffu, wy1, kp);
        int x0 = (int)bx0, y0 = (int)by0;
        float bwx0 = 1.f - bwx1, bwy0 = 1.f - bwy1;
        float4 acc = make_float4(0,0,0,0);
        bool vx0 = (unsigned)x0       < IMG;
        bool vx1 = (unsigned)(x0 + 1) < IMG;
        if ((unsigned)y0 < IMG) {
            const float* row = kvh + (size_t)(y0 * IMG) * 128 + coff;
            if (vx0) { float4 tv = *(const float4*)(row + (size_t)x0 * 128);
                float w = bwx0 * bwy0;
                acc.x += w*tv.x; acc.y += w*tv.y; acc.z += w*tv.z; acc.w += w*tv.w; }
            if (vx1) { float4 tv = *(const float4*)(row + (size_t)(x0+1) * 128);
                float w = bwx1 * bwy0;
                acc.x += w*tv.x; acc.y += w*tv.y; acc.z += w*tv.z; acc.w += w*tv.w; }
        }
        if ((unsigned)(y0 + 1) < IMG) {
            const float* row = kvh + (size_t)((y0+1) * IMG) * 128 + coff;
            if (vx0) { float4 tv = *(const float4*)(row + (size_t)x0 * 128);
                float w = bwx0 * bwy1;
                acc.x += w*tv.x; acc.y += w*tv.y; acc.z += w*tv.z; acc.w += w*tv.w; }
            if (vx1) { float4 tv = *(const float4*)(row + (size_t)(x0+1) * 128);
                float w = bwx1 * bwy1;
                acc.x += w*tv.x; acc.y += w*tv.y; acc.z += w*tv.z; acc.w += w*tv.w; }
        }
        // scores on k-half lanes; reduce within 16-lane groups
        float d0 = q0.x*acc.x + q0.y*acc.y + q0.z*acc.z + q0.w*acc.w;
        float d1 = q1.x*acc.x + q1.y*acc.y + q1.z*acc.z + q1.w*acc.w;
        float d2 = q2.x*acc.x + q2.y*acc.y + q2.z*acc.z + q2.w*acc.w;
#pragma unroll
        for (int off = 8; off > 0; off >>= 1) {
            d0 += __shfl_xor_sync(0xffffffffu, d0, off);
            d1 += __shfl_xor_sync(0xffffffffu, d1, off);
            d2 += __shfl_xor_sync(0xffffffffu, d2, off);
        }
        d0 = __shfl_sync(0xffffffffu, d0, lane & 15) * 0.125f;
        d1 = __shfl_sync(0xffffffffu, d1, lane & 15) * 0.125f;
        d2 = __shfl_sync(0xffffffffu, d2, lane & 15) * 0.125f;
        // streaming softmax (scores O(1): no running max needed in fp32)
        float e0 = __expf(d0), e1 = __expf(d1), e2 = __expf(d2);
        s0v += e0; s1v += e1; s2v += e2;
        o0.x += e0*acc.x; o0.y += e0*acc.y; o0.z += e0*acc.z; o0.w += e0*acc.w;
        o1.x += e1*acc.x; o1.y += e1*acc.y; o1.z += e1*acc.z; o1.w += e1*acc.w;
        o2.x += e2*acc.x; o2.y += e2*acc.y; o2.z += e2*acc.z; o2.w += e2*acc.w;
    }

    if (lane >= 16) {   // v-half lanes hold the weighted values
        float* orow = g_attn + (size_t)g * 3 * AD + h * HDIM + c4;
        float i0 = 1.f / s0v, i1 = 1.f / s1v, i2 = 1.f / s2v;
        *(float4*)(orow)          = make_float4(o0.x*i0, o0.y*i0, o0.z*i0, o0.w*i0);
        *(float4*)(orow + AD)     = make_float4(o1.x*i1, o1.y*i1, o1.z*i1, o1.w*i1);
        *(float4*)(orow + 2*AD)   = make_float4(o2.x*i2, o2.y*i2, o2.z*i2, o2.w*i2);
    }
}

// ---------------------------------------------------------------------------
// Kernel D: out = g_attn @ Wout + b_out + features.  M=24576, K=512, N=32.
// ---------------------------------------------------------------------------
__global__ __launch_bounds__(256) void out_gemm(
    const float* __restrict__ Wout, const float* __restrict__ b_out,
    const float* __restrict__ feat, float* __restrict__ out)
{
    const int r0 = blockIdx.x * 64;
    __shared__ float Xs[64][32];
    __shared__ float Ws[32][32];
    const int t = threadIdx.x;
    const int c = t & 31, rb = (t >> 5) * 8;
    float acc[8] = {0.f,0.f,0.f,0.f,0.f,0.f,0.f,0.f};

    for (int k0 = 0; k0 < AD; k0 += 32) {
#pragma unroll
        for (int rep = 0; rep < 8; rep++) {
            int idx = t + rep * 256;
            Xs[idx >> 5][idx & 31] =
                g_attn[(size_t)(r0 + (idx >> 5)) * AD + k0 + (idx & 31)];
        }
#pragma unroll
        for (int rep = 0; rep < 4; rep++) {
            int idx = t + rep * 256;
            Ws[idx >> 5][idx & 31] = Wout[(size_t)(k0 + (idx >> 5)) * GFDIM + (idx & 31)];
        }
        __syncthreads();
#pragma unroll
        for (int kk = 0; kk < 32; kk++) {
            float w = Ws[kk][c];
#pragma unroll
            for (int i = 0; i < 8; i++) acc[i] += Xs[rb + i][kk] * w;
        }
        __syncthreads();
    }
    float b = b_out[c];
#pragma unroll
    for (int i = 0; i < 8; i++) {
        int r = r0 + rb + i;
        out[(size_t)r * GFDIM + c] = acc[i] + b + feat[(size_t)r * GFDIM + c];
    }
}

// ---------------------------------------------------------------------------
extern "C" void kernel_launch(void* const* d_in, const int* in_sizes, int n_in,
                              void* d_out, int out_size)
{
    const float* means      = (const float*)d_in[0];
    const float* scales     = (const float*)d_in[1];
    const float* rotations  = (const float*)d_in[2];
    const float* features   = (const float*)d_in[3];
    const float* transforms = (const float*)d_in[4];
    const float* projection = (const float*)d_in[5];
    const float* image_feat = (const float*)d_in[6];
    const float* Wq         = (const float*)d_in[7];
    const float* Wk         = (const float*)d_in[8];
    const float* Wv         = (const float*)d_in[9];
    const float* W_off      = (const float*)d_in[10];
    const float* b_off      = (const float*)d_in[11];
    const float* Wout       = (const float*)d_in[12];
    const float* b_out      = (const float*)d_in[13];
    float* out = (float*)d_out;

    kv_gemm<<<dim3(NPIX / 64, AD / 128), 256>>>(image_feat, Wk, Wv);
    q_gemm<<<dim3(G_N * 3 / 64, AD / 256), 256>>>(features, Wq);
    attn_kernel<<<G_N, 256>>>(means, scales, rotations, transforms,
                              projection, W_off, b_off);
    out_gemm<<<G_N * 3 / 64, 256>>>(Wout, b_out, features, out);
}